// round 4
// baseline (speedup 1.0000x reference)
#include <cuda_runtime.h>
#include <cstdint>

#define N_LEAVES   16384
#define DIM        512
#define ROW_BYTES  (DIM * 4)               // 2048 B per row
#define K          3                       // subtree depth per block -> 8 leaves
#define LPB        (1 << K)                // 8
#define NBLOCKS    (N_LEAVES / LPB)        // 2048
#define ROOT_LEVEL (DEPTH_ - K)            // 11
#define DEPTH_     14
#define N_UPPER    ((1 << 11) - 1)         // 2047 nodes at levels 0..10
#define MIN_DIST   1e-7f

// Dynamic smem layout (bytes)
#define OFF_MBAR 0
#define OFF_X    128
#define OFF_DC   (OFF_X  + LPB * ROW_BYTES)          // leaf rows  (level 14), 16 KB
#define OFF_DB   (OFF_DC + LPB * ROW_BYTES)          // level 13,   8 KB
#define OFF_DA   (OFF_DB + (LPB / 2) * ROW_BYTES)    // level 12,   4 KB
#define OFF_DR   (OFF_DA + (LPB / 4) * ROW_BYTES)    // level 11,   2 KB
#define OFF_PD   (OFF_DR + ROW_BYTES)                // dot partials, 4 KB
#define OFF_SACC (OFF_PD + LPB * 128 * 4)
#define SMEM_TOTAL (OFF_SACC + 64)
#define TX_BYTES ((LPB + LPB + LPB / 2 + LPB / 4 + 1) * ROW_BYTES)  // 47104

__device__ double        g_acc;    // zero-init; reset by last block each run
__device__ unsigned int  g_count;

__device__ __forceinline__ uint32_t smem_u32(const void* p) {
    uint32_t a;
    asm("{ .reg .u64 t; cvta.to.shared.u64 t, %1; cvt.u32.u64 %0, t; }"
        : "=r"(a) : "l"(p));
    return a;
}

__device__ __forceinline__ void bulk_g2s(uint32_t dst, const void* src,
                                         uint32_t bytes, uint32_t mbar) {
    asm volatile(
        "cp.async.bulk.shared::cluster.global.mbarrier::complete_tx::bytes "
        "[%0], [%1], %2, [%3];"
        :: "r"(dst), "l"(src), "r"(bytes), "r"(mbar) : "memory");
}

__device__ __forceinline__ float sq4(float4 d) {
    return d.x * d.x + d.y * d.y + d.z * d.z + d.w * d.w;
}

__global__ void __launch_bounds__(128)
tm_fused_kernel(const float* __restrict__ x,
                const float* __restrict__ deltas,
                const float* __restrict__ heights,
                float* __restrict__ out) {
    extern __shared__ char smem[];
    float*  pd   = (float*)(smem + OFF_PD);
    double* sacc = (double*)(smem + OFF_SACC);

    const int tid = threadIdx.x;       // owns float4 slice [tid*4, tid*4+4)
    const int bi  = blockIdx.x;        // subtree index (level-11 node = bi + 2047)
    const uint32_t mbar = smem_u32(smem + OFF_MBAR);
    float facc = 0.f;

    // ── Issue all bulk copies up front (one thread, one mbarrier) ──
    if (tid == 0) {
        asm volatile("mbarrier.init.shared.b64 [%0], 1;" :: "r"(mbar) : "memory");
    }
    __syncthreads();
    if (tid == 0) {
        asm volatile("mbarrier.arrive.expect_tx.shared.b64 _, [%0], %1;"
                     :: "r"(mbar), "r"((uint32_t)TX_BYTES) : "memory");
        bulk_g2s(smem_u32(smem + OFF_X),  x      + (size_t)bi * LPB * DIM,
                 LPB * ROW_BYTES, mbar);
        bulk_g2s(smem_u32(smem + OFF_DC), deltas + (size_t)(bi * LPB + (N_LEAVES - 1)) * DIM,
                 LPB * ROW_BYTES, mbar);
        bulk_g2s(smem_u32(smem + OFF_DB), deltas + (size_t)(bi * (LPB / 2) + (N_LEAVES / 2 - 1)) * DIM,
                 (LPB / 2) * ROW_BYTES, mbar);
        bulk_g2s(smem_u32(smem + OFF_DA), deltas + (size_t)(bi * (LPB / 4) + (N_LEAVES / 4 - 1)) * DIM,
                 (LPB / 4) * ROW_BYTES, mbar);
        bulk_g2s(smem_u32(smem + OFF_DR), deltas + (size_t)(bi + N_UPPER) * DIM,
                 ROW_BYTES, mbar);
    }

    // ── Overlap: upper-node duty + common path levels 0..10 via LDG (L2-hot) ──
    if (bi < N_UPPER) {
        float4 d = ((const float4*)(deltas + (size_t)bi * DIM))[tid];
        float s = sq4(d);
        if (bi == 0) facc += s;
        else facc += __fdividef(s, fmaxf(heights[bi] - heights[(bi - 1) >> 1], MIN_DIST));
    }
    float4 wc = make_float4(0.f, 0.f, 0.f, 0.f);
    #pragma unroll
    for (int l = 0; l <= 10; l++) {
        int node = (bi >> (11 - l)) + ((1 << l) - 1);
        float4 d = ((const float4*)(deltas + (size_t)node * DIM))[tid];
        wc.x += d.x; wc.y += d.y; wc.z += d.z; wc.w += d.w;
    }

    // ── Wait for bulk data ──
    {
        uint32_t done;
        asm volatile(
            "{\n\t.reg .pred p;\n\t"
            "mbarrier.try_wait.parity.acquire.cta.shared::cta.b64 p, [%1], 0;\n\t"
            "selp.b32 %0, 1, 0, p;\n\t}"
            : "=r"(done) : "r"(mbar) : "memory");
        while (!done) {
            asm volatile(
                "{\n\t.reg .pred p;\n\t"
                "mbarrier.try_wait.parity.acquire.cta.shared::cta.b64 p, [%1], 0, 0x989680;\n\t"
                "selp.b32 %0, 1, 0, p;\n\t}"
                : "=r"(done) : "r"(mbar) : "memory");
        }
    }

    // Level-11 row (uniquely owned by this block): fold into wc + sq term.
    {
        float4 d = ((const float4*)(smem + OFF_DR))[tid];
        wc.x += d.x; wc.y += d.y; wc.z += d.z; wc.w += d.w;
        int node = bi + N_UPPER;
        facc += __fdividef(sq4(d),
            fmaxf(heights[node] - heights[(node - 1) >> 1], MIN_DIST));
    }

    // ── Per-leaf compute from smem (LDS, cheap) ──
    const float4* xs = (const float4*)(smem + OFF_X);
    const float4* cs = (const float4*)(smem + OFF_DC);
    const float4* bs = (const float4*)(smem + OFF_DB);
    const float4* as = (const float4*)(smem + OFF_DA);
    #pragma unroll
    for (int j = 0; j < LPB; j++) {
        const int i   = bi * LPB + j;
        const int n_c = i + (N_LEAVES - 1);
        const int n_b = (i >> 1) + (N_LEAVES / 2 - 1);
        const int n_a = (i >> 2) + (N_LEAVES / 4 - 1);

        float4 xv = xs[j * 128 + tid];
        float4 dc = cs[j * 128 + tid];
        float4 db = bs[(j >> 1) * 128 + tid];
        float4 da = as[(j >> 2) * 128 + tid];

        float tx = wc.x + da.x + db.x + dc.x;
        float ty = wc.y + da.y + db.y + dc.y;
        float tz = wc.z + da.z + db.z + dc.z;
        float tw = wc.w + da.w + db.w + dc.w;
        pd[j * 128 + tid] = xv.x * tx + xv.y * ty + xv.z * tz + xv.w * tw;

        facc += __fdividef(sq4(dc), fmaxf(heights[n_c] - heights[n_b], MIN_DIST));
        if ((j & 1) == 0)
            facc += __fdividef(sq4(db), fmaxf(heights[n_b] - heights[n_a], MIN_DIST));
        if ((j & 3) == 0)
            facc += __fdividef(sq4(da),
                fmaxf(heights[n_a] - heights[(n_a - 1) >> 1], MIN_DIST));
    }

    // ── Block reductions ──
    double acc = (double)facc;
    #pragma unroll
    for (int off = 16; off; off >>= 1)
        acc += __shfl_down_sync(0xffffffffu, acc, off);
    int warp = tid >> 5, lane = tid & 31;
    if (lane == 0) sacc[warp] = acc;
    __syncthreads();

    #pragma unroll
    for (int j = warp * 2; j < warp * 2 + 2; j++) {
        float v = pd[j * 128 + lane]      + pd[j * 128 + lane + 32]
                + pd[j * 128 + lane + 64] + pd[j * 128 + lane + 96];
        #pragma unroll
        for (int off = 16; off; off >>= 1) v += __shfl_down_sync(0xffffffffu, v, off);
        if (lane == 0) out[bi * LPB + j] = v;
    }

    // ── Scalar epilogue: last block writes delta_total and resets state ──
    if (tid == 0) {
        atomicAdd(&g_acc, sacc[0] + sacc[1] + sacc[2] + sacc[3]);
        __threadfence();
        unsigned int prev = atomicAdd(&g_count, 1u);
        if (prev == (unsigned int)(gridDim.x - 1)) {
            out[N_LEAVES] = (float)(*(volatile double*)&g_acc);
            g_acc   = 0.0;   // graph-replay safe
            g_count = 0u;
        }
    }
}

extern "C" void kernel_launch(void* const* d_in, const int* in_sizes, int n_in,
                              void* d_out, int out_size) {
    const float* x       = (const float*)d_in[0];
    const float* deltas  = (const float*)d_in[1];
    const float* heights = (const float*)d_in[2];
    float* out = (float*)d_out;

    cudaFuncSetAttribute(tm_fused_kernel,
                         cudaFuncAttributeMaxDynamicSharedMemorySize, SMEM_TOTAL);
    tm_fused_kernel<<<NBLOCKS, 128, SMEM_TOTAL>>>(x, deltas, heights, out);
}

// round 8
// speedup vs baseline: 1.1132x; 1.1132x over previous
#include <cuda_runtime.h>

#define N_LEAVES   16384
#define DIM        512
#define DEPTH      14
#define K          3                       // subtree depth per block -> 8 leaves
#define LPB        (1 << K)                // 8 leaves per block
#define NBLOCKS    (N_LEAVES / LPB)        // 2048
#define ROOT_LEVEL (DEPTH - K)             // 11
#define N_UPPER    ((1 << ROOT_LEVEL) - 1) // 2047 nodes at levels 0..10
#define MIN_DIST   1e-7f

__device__ double        g_acc;    // zero-init; reset by last block each run
__device__ unsigned int  g_count;

__device__ __forceinline__ float sq4(float4 d) {
    return d.x * d.x + d.y * d.y + d.z * d.z + d.w * d.w;
}

// Streaming (evict-first) float4 load for single-use data.
__device__ __forceinline__ float4 ldcs4(const float4* p) {
    float4 v;
    asm volatile("ld.global.cs.v4.f32 {%0,%1,%2,%3}, [%4];"
                 : "=f"(v.x), "=f"(v.y), "=f"(v.z), "=f"(v.w) : "l"(p));
    return v;
}

__global__ void __launch_bounds__(128, 10)
tm_fused_kernel(const float* __restrict__ x,
                const float* __restrict__ deltas,
                const float* __restrict__ heights,
                float* __restrict__ out) {
    __shared__ float  pd[LPB * 128];   // deferred per-leaf dot partials (4 KB)
    __shared__ double sacc[4];

    const int tid = threadIdx.x;       // owns float4 slice [tid*4, tid*4+4)
    const int bi  = blockIdx.x;        // subtree index (level-11 node = bi + 2047)
    float facc0 = 0.f, facc1 = 0.f;    // split accumulators (shorter dep chain)

    // Upper-node duty: block bi (< 2047) owns node bi's sq/branch term.
    // These rows are other blocks' common-path rows -> default policy (L2-hot).
    if (bi < N_UPPER) {
        float4 d = ((const float4*)(deltas + (size_t)bi * DIM))[tid];
        float s = sq4(d);
        if (bi == 0) facc0 += s;
        else facc0 += __fdividef(s, fmaxf(heights[bi] - heights[(bi - 1) >> 1], MIN_DIST));
    }

    // Common path: levels 0..ROOT_LEVEL summed once (independent loads, L2-hot).
    float4 wc = make_float4(0.f, 0.f, 0.f, 0.f);
    #pragma unroll
    for (int l = 0; l <= ROOT_LEVEL; l++) {
        int node = (bi >> (ROOT_LEVEL - l)) + ((1 << l) - 1);
        float4 d = ((const float4*)(deltas + (size_t)node * DIM))[tid];
        wc.x += d.x; wc.y += d.y; wc.z += d.z; wc.w += d.w;
        if (l == ROOT_LEVEL) {  // level-11 node uniquely owned by this block
            facc1 += __fdividef(sq4(d),
                fmaxf(heights[node] - heights[(node - 1) >> 1], MIN_DIST));
        }
    }

    // Flat per-leaf loads: 4 independent loads per leaf, no carried chain.
    // x and leaf-delta rows are single-use -> streaming loads (evict-first).
    // Level-13/12 rows are reused within the block -> default policy (L1 hits).
    #pragma unroll
    for (int j = 0; j < LPB; j++) {
        const int i   = bi * LPB + j;
        const int n_c = i + (N_LEAVES - 1);            // level 14 (leaf)
        const int n_b = (i >> 1) + (N_LEAVES / 2 - 1); // level 13
        const int n_a = (i >> 2) + (N_LEAVES / 4 - 1); // level 12

        float4 xv = ldcs4(&((const float4*)(x      + (size_t)i   * DIM))[tid]);
        float4 dc = ldcs4(&((const float4*)(deltas + (size_t)n_c * DIM))[tid]);
        float4 db = ((const float4*)(deltas + (size_t)n_b * DIM))[tid];
        float4 da = ((const float4*)(deltas + (size_t)n_a * DIM))[tid];

        float tx = wc.x + da.x + db.x + dc.x;
        float ty = wc.y + da.y + db.y + dc.y;
        float tz = wc.z + da.z + db.z + dc.z;
        float tw = wc.w + da.w + db.w + dc.w;
        pd[j * 128 + tid] = xv.x * tx + xv.y * ty + xv.z * tz + xv.w * tw;

        // sq/branch: count each node exactly once (guards on j).
        facc0 += __fdividef(sq4(dc), fmaxf(heights[n_c] - heights[n_b], MIN_DIST));
        if ((j & 1) == 0)
            facc1 += __fdividef(sq4(db), fmaxf(heights[n_b] - heights[n_a], MIN_DIST));
        if ((j & 3) == 0)
            facc0 += __fdividef(sq4(da),
                fmaxf(heights[n_a] - heights[(n_a - 1) >> 1], MIN_DIST));
    }

    // Reduce fused sq accumulator across the block (double from here on).
    double acc = (double)(facc0 + facc1);
    #pragma unroll
    for (int off = 16; off; off >>= 1)
        acc += __shfl_down_sync(0xffffffffu, acc, off);
    int warp = tid >> 5, lane = tid & 31;
    if (lane == 0) sacc[warp] = acc;
    __syncthreads();

    // Batched dot reductions: warp w reduces leaves [2w, 2w+2).
    #pragma unroll
    for (int j = warp * 2; j < warp * 2 + 2; j++) {
        float v = pd[j * 128 + lane]      + pd[j * 128 + lane + 32]
                + pd[j * 128 + lane + 64] + pd[j * 128 + lane + 96];
        #pragma unroll
        for (int off = 16; off; off >>= 1) v += __shfl_down_sync(0xffffffffu, v, off);
        if (lane == 0) out[bi * LPB + j] = v;
    }

    // Scalar epilogue: last block writes delta_total and resets state.
    if (tid == 0) {
        atomicAdd(&g_acc, sacc[0] + sacc[1] + sacc[2] + sacc[3]);
        __threadfence();
        unsigned int prev = atomicAdd(&g_count, 1u);
        if (prev == (unsigned int)(gridDim.x - 1)) {
            out[N_LEAVES] = (float)(*(volatile double*)&g_acc);
            g_acc   = 0.0;   // graph-replay safe
            g_count = 0u;
        }
    }
}

extern "C" void kernel_launch(void* const* d_in, const int* in_sizes, int n_in,
                              void* d_out, int out_size) {
    const float* x       = (const float*)d_in[0];
    const float* deltas  = (const float*)d_in[1];
    const float* heights = (const float*)d_in[2];
    float* out = (float*)d_out;

    tm_fused_kernel<<<NBLOCKS, 128>>>(x, deltas, heights, out);
}

// round 10
// speedup vs baseline: 1.3316x; 1.1963x over previous
#include <cuda_runtime.h>

#define N_LEAVES   16384
#define DIM        512
#define DEPTH      14
#define K          3                       // subtree depth per block -> 8 leaves
#define LPB        (1 << K)                // 8 leaves per block
#define NBLOCKS    (N_LEAVES / LPB)        // 2048
#define ROOT_LEVEL (DEPTH - K)             // 11
#define N_UPPER    ((1 << ROOT_LEVEL) - 1) // 2047 nodes at levels 0..10
#define MIN_DIST   1e-7f

__device__ double        g_acc;    // zero-init; reset by last block each run
__device__ unsigned int  g_count;

__device__ __forceinline__ float sq4(float4 d) {
    return d.x * d.x + d.y * d.y + d.z * d.z + d.w * d.w;
}

__global__ void __launch_bounds__(128, 6)
tm_fused_kernel(const float* __restrict__ x,
                const float* __restrict__ deltas,
                const float* __restrict__ heights,
                float* __restrict__ out) {
    __shared__ float  pd[LPB * 128];   // deferred per-leaf dot partials (4 KB)
    __shared__ double sacc[4];

    const int tid = threadIdx.x;       // owns float4 slice [tid*4, tid*4+4)
    const int bi  = blockIdx.x;        // subtree index (level-11 node = bi + 2047)
    float facc0 = 0.f, facc1 = 0.f;    // split accumulators (shorter dep chain)

    // Upper-node duty: block bi (< 2047) owns node bi's sq/branch term (L2-hot).
    if (bi < N_UPPER) {
        float4 d = ((const float4*)(deltas + (size_t)bi * DIM))[tid];
        float s = sq4(d);
        if (bi == 0) facc0 += s;
        else facc0 += __fdividef(s, fmaxf(heights[bi] - heights[(bi - 1) >> 1], MIN_DIST));
    }

    // Common path: levels 0..ROOT_LEVEL summed once (independent loads, L2-hot).
    float4 wc = make_float4(0.f, 0.f, 0.f, 0.f);
    #pragma unroll
    for (int l = 0; l <= ROOT_LEVEL; l++) {
        int node = (bi >> (ROOT_LEVEL - l)) + ((1 << l) - 1);
        float4 d = ((const float4*)(deltas + (size_t)node * DIM))[tid];
        wc.x += d.x; wc.y += d.y; wc.z += d.z; wc.w += d.w;
        if (l == ROOT_LEVEL) {  // level-11 node uniquely owned by this block
            facc1 += __fdividef(sq4(d),
                fmaxf(heights[node] - heights[(node - 1) >> 1], MIN_DIST));
        }
    }

    // Leaf phase: 2 quads x 2 pairs x 2 leaves, fully unrolled.
    // Shared ancestor rows loaded exactly ONCE (da per quad, db per pair):
    // 22 row-loads per block instead of 32, all independent -> deep batching.
    #pragma unroll
    for (int q = 0; q < 2; q++) {
        const int i_q = bi * LPB + q * 4;
        const int n_a = (i_q >> 2) + (N_LEAVES / 4 - 1);   // level-12 node
        float4 da = ((const float4*)(deltas + (size_t)n_a * DIM))[tid];
        facc0 += __fdividef(sq4(da),
            fmaxf(heights[n_a] - heights[(n_a - 1) >> 1], MIN_DIST));

        #pragma unroll
        for (int p = 0; p < 2; p++) {
            const int j  = q * 4 + p * 2;                  // even leaf of pair
            const int i  = bi * LPB + j;
            const int n_b = (i >> 1) + (N_LEAVES / 2 - 1); // level-13 node
            const int n_c0 = i + (N_LEAVES - 1);           // leaf nodes
            const int n_c1 = n_c0 + 1;

            float4 db  = ((const float4*)(deltas + (size_t)n_b  * DIM))[tid];
            float4 xv0 = ((const float4*)(x      + (size_t)i       * DIM))[tid];
            float4 xv1 = ((const float4*)(x      + (size_t)(i + 1) * DIM))[tid];
            float4 dc0 = ((const float4*)(deltas + (size_t)n_c0 * DIM))[tid];
            float4 dc1 = ((const float4*)(deltas + (size_t)n_c1 * DIM))[tid];

            float bx = wc.x + da.x + db.x;
            float by = wc.y + da.y + db.y;
            float bz = wc.z + da.z + db.z;
            float bw = wc.w + da.w + db.w;

            pd[j * 128 + tid] =
                xv0.x * (bx + dc0.x) + xv0.y * (by + dc0.y) +
                xv0.z * (bz + dc0.z) + xv0.w * (bw + dc0.w);
            pd[(j + 1) * 128 + tid] =
                xv1.x * (bx + dc1.x) + xv1.y * (by + dc1.y) +
                xv1.z * (bz + dc1.z) + xv1.w * (bw + dc1.w);

            float hb = heights[n_b];
            facc0 += __fdividef(sq4(dc0), fmaxf(heights[n_c0] - hb, MIN_DIST));
            facc1 += __fdividef(sq4(dc1), fmaxf(heights[n_c1] - hb, MIN_DIST));
            facc1 += __fdividef(sq4(db),  fmaxf(hb - heights[n_a], MIN_DIST));
        }
    }

    // Reduce fused sq accumulator across the block (double from here on).
    double acc = (double)(facc0 + facc1);
    #pragma unroll
    for (int off = 16; off; off >>= 1)
        acc += __shfl_down_sync(0xffffffffu, acc, off);
    int warp = tid >> 5, lane = tid & 31;
    if (lane == 0) sacc[warp] = acc;
    __syncthreads();

    // Batched dot reductions: warp w reduces leaves [2w, 2w+2).
    #pragma unroll
    for (int j = warp * 2; j < warp * 2 + 2; j++) {
        float v = pd[j * 128 + lane]      + pd[j * 128 + lane + 32]
                + pd[j * 128 + lane + 64] + pd[j * 128 + lane + 96];
        #pragma unroll
        for (int off = 16; off; off >>= 1) v += __shfl_down_sync(0xffffffffu, v, off);
        if (lane == 0) out[bi * LPB + j] = v;
    }

    // Scalar epilogue: last block writes delta_total and resets state.
    if (tid == 0) {
        atomicAdd(&g_acc, sacc[0] + sacc[1] + sacc[2] + sacc[3]);
        __threadfence();
        unsigned int prev = atomicAdd(&g_count, 1u);
        if (prev == (unsigned int)(gridDim.x - 1)) {
            out[N_LEAVES] = (float)(*(volatile double*)&g_acc);
            g_acc   = 0.0;   // graph-replay safe
            g_count = 0u;
        }
    }
}

extern "C" void kernel_launch(void* const* d_in, const int* in_sizes, int n_in,
                              void* d_out, int out_size) {
    const float* x       = (const float*)d_in[0];
    const float* deltas  = (const float*)d_in[1];
    const float* heights = (const float*)d_in[2];
    float* out = (float*)d_out;

    tm_fused_kernel<<<NBLOCKS, 128>>>(x, deltas, heights, out);
}